// round 6
// baseline (speedup 1.0000x reference)
#include <cuda_runtime.h>

#define BQ 64
#define NQ 64
#define TQ 4096
#define BN (BQ * NQ)   // 4096 floats per time slice

// Scratch (module-load allocated): E = exp(emissions) in [t][b][j] layout,
// plus linear-domain alpha/beta (arbitrary per-(b,t) scale; cancels in gamma).
__device__ float g_E[TQ * BN];
__device__ float g_alpha[TQ * BN];
__device__ float g_beta[TQ * BN];

// ---- packed f32x2 helpers (Blackwell; one instr = 2 fp32 ops) ----
__device__ __forceinline__ void fma2(unsigned long long& d,
                                     unsigned long long a, unsigned long long b) {
    asm("fma.rn.f32x2 %0, %1, %2, %0;" : "+l"(d) : "l"(a), "l"(b));
}
__device__ __forceinline__ unsigned long long add2(unsigned long long a,
                                                   unsigned long long b) {
    unsigned long long d;
    asm("add.rn.f32x2 %0, %1, %2;" : "=l"(d) : "l"(a), "l"(b));
    return d;
}
__device__ __forceinline__ unsigned long long pack2(float lo, float hi) {
    unsigned long long d;
    asm("mov.b64 %0, {%1, %2};" : "=l"(d) : "f"(lo), "f"(hi));
    return d;
}
__device__ __forceinline__ float2 unpack2(unsigned long long v) {
    float2 r;
    asm("mov.b64 {%0, %1}, %2;" : "=f"(r.x), "=f"(r.y) : "l"(v));
    return r;
}

// ---------------------------------------------------------------------------
// Kernel 1: E[t][b][j] = exp(emissions[b][j][t])  (tiled transpose via shared)
// ---------------------------------------------------------------------------
__global__ void __launch_bounds__(256) expT_kernel(const float* __restrict__ em) {
    __shared__ float tile[64][65];
    int b  = blockIdx.y;
    int t0 = blockIdx.x * 64;
    int tid = threadIdx.x;
    int c  = tid & 63;
    int r4 = tid >> 6;

#pragma unroll
    for (int rep = 0; rep < 16; rep++) {
        int j = rep * 4 + r4;
        tile[j][c] = __expf(em[b * NQ * TQ + j * TQ + t0 + c]);
    }
    __syncthreads();
#pragma unroll
    for (int rep = 0; rep < 16; rep++) {
        int tt = rep * 4 + r4;
        g_E[(t0 + tt) * BN + b * NQ + c] = tile[c][tt];
    }
}

// ---------------------------------------------------------------------------
// Kernel 2: forward/backward linear-domain scans.
// grid (B, 2), 128 threads. Thread pair (j = tid>>1, h = tid&1) splits state
// j's 64-term dot in half: 16 packed f32x2 FMAs each, combined via shfl_xor(1).
// Renorm every 8 steps, PIPELINED (measured at t%8==7 fwd / ==0 bwd, applied
// one step later; uniform scale cancels in gamma).
// E prefetch: 8 named register slots, distance 8, loops unrolled by 8.
// ---------------------------------------------------------------------------

#define DOT_HALF(PBUF)                                                         \
    const ulonglong2* pv = (const ulonglong2*)&psh[PBUF][h * 32];              \
    unsigned long long ac0 = 0, ac1 = 0, ac2 = 0, ac3 = 0;                     \
    _Pragma("unroll")                                                          \
    for (int k = 0; k < 8; k++) {                                              \
        ulonglong2 q = pv[k];                                                  \
        fma2((k & 1) ? ac2 : ac0, q.x, Apk[2 * k]);                            \
        fma2((k & 1) ? ac3 : ac1, q.y, Apk[2 * k + 1]);                        \
    }                                                                          \
    float2 fr = unpack2(add2(add2(ac0, ac1), add2(ac2, ac3)));                 \
    float hf = fr.x + fr.y;                                                    \
    float v2 = hf + __shfl_xor_sync(0xffffffffu, hf, 1);

#define REDUCE_PUB()                                                           \
    {                                                                          \
        float s = v2;                                                          \
        s += __shfl_xor_sync(0xffffffffu, s, 2);                               \
        s += __shfl_xor_sync(0xffffffffu, s, 4);                               \
        s += __shfl_xor_sync(0xffffffffu, s, 8);                               \
        s += __shfl_xor_sync(0xffffffffu, s, 16);                              \
        if (lane == 0) red2[w] = s;                                            \
    }

// forward step at time T: consumes EREG = E[T]; refills EREG with E[T+8]
#define FWD_STEP(T, EREG, APPLY, REDUCE) do {                                  \
    float e_new = g_E[(((T) + 8 < TQ) ? (T) + 8 : TQ - 1) * BN + ebase];       \
    if (APPLY) {                                                               \
        float4 r4 = *(const float4*)red2;                                      \
        inv_s = __frcp_rn((r4.x + r4.y) + (r4.z + r4.w));                      \
    }                                                                          \
    DOT_HALF(((T) - 1) & 1)                                                    \
    if (APPLY) v2 *= inv_s;                                                    \
    v2 *= (EREG);                                                              \
    if (REDUCE) REDUCE_PUB()                                                   \
    if (h == 0) {                                                              \
        psh[(T) & 1][j] = v2;                                                  \
        g_alpha[(T) * BN + ebase] = v2;                                        \
    }                                                                          \
    __syncthreads();                                                           \
    (EREG) = e_new;                                                            \
} while (0)

// backward step at time T: EREG = E[T] feeds the carry; refills with E[T-8]
#define BWD_STEP(T, EREG, APPLY, REDUCE) do {                                  \
    float e_new = g_E[(((T) >= 8) ? (T) - 8 : 0) * BN + ebase];                \
    if (APPLY) {                                                               \
        float4 r4 = *(const float4*)red2;                                      \
        inv_s = __frcp_rn((r4.x + r4.y) + (r4.z + r4.w));                      \
    }                                                                          \
    DOT_HALF(((T) + 1) & 1)                                                    \
    if (APPLY) v2 *= inv_s;                                                    \
    if (REDUCE) REDUCE_PUB()                                                   \
    if (h == 0) {                                                              \
        g_beta[(T) * BN + ebase] = v2;                                         \
        psh[(T) & 1][j] = v2 * (EREG);                                         \
    }                                                                          \
    __syncthreads();                                                           \
    (EREG) = e_new;                                                            \
} while (0)

__global__ void __launch_bounds__(128) scan_kernel(const float* __restrict__ trans,
                                                   const float* __restrict__ init) {
    const int b    = blockIdx.x;
    const int dir  = blockIdx.y;
    const int tid  = threadIdx.x;
    const int j    = tid >> 1;   // state index 0..63
    const int h    = tid & 1;    // which half of the dot
    const int lane = tid & 31;
    const int w    = tid >> 5;

    __shared__ __align__(16) float psh[2][64];
    __shared__ __align__(16) float red2[4];

    // per-thread half-row/column of A, packed in 16 x f32x2 registers.
    // Pairing matches DOT_HALF: Apk[2k] multiplies states (32h+4k, 32h+4k+1),
    // Apk[2k+1] multiplies states (32h+4k+2, 32h+4k+3).
    unsigned long long Apk[16];
    if (dir == 0) {
        // fwd needs A[i][j] (strided loads, one-time)
#pragma unroll
        for (int k = 0; k < 8; k++) {
            int i0 = 32 * h + 4 * k;
            Apk[2 * k]     = pack2(trans[(i0    ) * NQ + j], trans[(i0 + 1) * NQ + j]);
            Apk[2 * k + 1] = pack2(trans[(i0 + 2) * NQ + j], trans[(i0 + 3) * NQ + j]);
        }
    } else {
        // bwd needs A[j][i] (contiguous)
        const float4* rp = (const float4*)(trans + j * NQ + 32 * h);
#pragma unroll
        for (int k = 0; k < 8; k++) {
            float4 a = rp[k];
            Apk[2 * k]     = pack2(a.x, a.y);
            Apk[2 * k + 1] = pack2(a.z, a.w);
        }
    }

    const int ebase = b * NQ + j;
    float inv_s = 1.0f;

    if (dir == 0) {
        // ---------------- forward ----------------
        float v0 = init[j] * g_E[0 * BN + ebase];
        if (h == 0) {
            psh[0][j] = v0;
            g_alpha[0 * BN + ebase] = v0;
        }
        // prefill E slots with E[1..8]
        float e0 = g_E[1 * BN + ebase], e1 = g_E[2 * BN + ebase];
        float e2 = g_E[3 * BN + ebase], e3 = g_E[4 * BN + ebase];
        float e4 = g_E[5 * BN + ebase], e5 = g_E[6 * BN + ebase];
        float e6 = g_E[7 * BN + ebase], e7 = g_E[8 * BN + ebase];
        __syncthreads();

        // prologue t = 1..8 (renorm measured at 7, applied at 8)
        FWD_STEP(1, e0, 0, 0); FWD_STEP(2, e1, 0, 0);
        FWD_STEP(3, e2, 0, 0); FWD_STEP(4, e3, 0, 0);
        FWD_STEP(5, e4, 0, 0); FWD_STEP(6, e5, 0, 0);
        FWD_STEP(7, e6, 0, 1); FWD_STEP(8, e7, 1, 0);

        // main: t0 = 9, 17, ..., 4081  (covers 9..4088)
        for (int t0 = 9; t0 <= TQ - 15; t0 += 8) {
            FWD_STEP(t0,     e0, 0, 0); FWD_STEP(t0 + 1, e1, 0, 0);
            FWD_STEP(t0 + 2, e2, 0, 0); FWD_STEP(t0 + 3, e3, 0, 0);
            FWD_STEP(t0 + 4, e4, 0, 0); FWD_STEP(t0 + 5, e5, 0, 0);
            FWD_STEP(t0 + 6, e6, 0, 1); FWD_STEP(t0 + 7, e7, 1, 0);
        }

        // epilogue t = 4089..4095 (no renorm needed)
        FWD_STEP(TQ - 7, e0, 0, 0); FWD_STEP(TQ - 6, e1, 0, 0);
        FWD_STEP(TQ - 5, e2, 0, 0); FWD_STEP(TQ - 4, e3, 0, 0);
        FWD_STEP(TQ - 3, e4, 0, 0); FWD_STEP(TQ - 2, e5, 0, 0);
        FWD_STEP(TQ - 1, e6, 0, 0);
    } else {
        // ---------------- backward ----------------
        float eT = g_E[(TQ - 1) * BN + ebase];
        if (h == 0) {
            g_beta[(TQ - 1) * BN + ebase] = 1.0f;
            psh[(TQ - 1) & 1][j] = eT;   // carry = beta_{T-1} * E_{T-1}
        }
        // prefill E slots with E[4094..4087]
        float e0 = g_E[(TQ - 2) * BN + ebase], e1 = g_E[(TQ - 3) * BN + ebase];
        float e2 = g_E[(TQ - 4) * BN + ebase], e3 = g_E[(TQ - 5) * BN + ebase];
        float e4 = g_E[(TQ - 6) * BN + ebase], e5 = g_E[(TQ - 7) * BN + ebase];
        float e6 = g_E[(TQ - 8) * BN + ebase], e7 = g_E[(TQ - 9) * BN + ebase];
        __syncthreads();

        // prologue t = 4094..4087 (renorm measured at 4088, applied at 4087)
        BWD_STEP(TQ - 2, e0, 0, 0); BWD_STEP(TQ - 3, e1, 0, 0);
        BWD_STEP(TQ - 4, e2, 0, 0); BWD_STEP(TQ - 5, e3, 0, 0);
        BWD_STEP(TQ - 6, e4, 0, 0); BWD_STEP(TQ - 7, e5, 0, 0);
        BWD_STEP(TQ - 8, e6, 0, 1); BWD_STEP(TQ - 9, e7, 1, 0);

        // main: t0 = 4086 down to 14 (covers 4086..7)
        for (int t0 = TQ - 10; t0 >= 14; t0 -= 8) {
            BWD_STEP(t0,     e0, 0, 0); BWD_STEP(t0 - 1, e1, 0, 0);
            BWD_STEP(t0 - 2, e2, 0, 0); BWD_STEP(t0 - 3, e3, 0, 0);
            BWD_STEP(t0 - 4, e4, 0, 0); BWD_STEP(t0 - 5, e5, 0, 0);
            BWD_STEP(t0 - 6, e6, 0, 1); BWD_STEP(t0 - 7, e7, 1, 0);
        }

        // epilogue t = 6..0
        BWD_STEP(6, e0, 0, 0); BWD_STEP(5, e1, 0, 0);
        BWD_STEP(4, e2, 0, 0); BWD_STEP(3, e3, 0, 0);
        BWD_STEP(2, e4, 0, 0); BWD_STEP(1, e5, 0, 0);
        BWD_STEP(0, e6, 0, 0);
    }
}

// ---------------------------------------------------------------------------
// Kernel 3: gamma. g = log(alpha)+log(beta); out = g - LSE_j(g).
// Scales cancel. Tiled so output writes coalesce along t.
// ---------------------------------------------------------------------------
__global__ void __launch_bounds__(256) gamma_kernel(float* __restrict__ out) {
    __shared__ float gsh[64][33];
    __shared__ float part[8][32];
    __shared__ float lse[32];

    int b   = blockIdx.y;
    int t0  = blockIdx.x * 32;
    int tid = threadIdx.x;
    int c   = tid & 63;
    int r   = tid >> 6;

#pragma unroll
    for (int rep = 0; rep < 8; rep++) {
        int tt  = rep * 4 + r;
        int idx = (t0 + tt) * BN + b * NQ + c;
        gsh[c][tt] = __logf(g_alpha[idx]) + __logf(g_beta[idx]);
    }
    __syncthreads();

    int tt  = tid & 31;
    int seg = tid >> 5;

    float m = -3.4e38f;
#pragma unroll
    for (int k = 0; k < 8; k++) m = fmaxf(m, gsh[seg * 8 + k][tt]);
    part[seg][tt] = m;
    __syncthreads();

    if (seg == 0) {
        float mm = part[0][tt];
#pragma unroll
        for (int k = 1; k < 8; k++) mm = fmaxf(mm, part[k][tt]);
        lse[tt] = mm;
    }
    __syncthreads();

    float mm = lse[tt];
    float ss = 0.f;
#pragma unroll
    for (int k = 0; k < 8; k++) ss += __expf(gsh[seg * 8 + k][tt] - mm);
    part[seg][tt] = ss;
    __syncthreads();

    if (seg == 0) {
        float s = 0.f;
#pragma unroll
        for (int k = 0; k < 8; k++) s += part[k][tt];
        lse[tt] = mm + __logf(s);
    }
    __syncthreads();

    float l = lse[tt];
#pragma unroll
    for (int rep = 0; rep < 8; rep++) {
        int jj = rep * 8 + seg;
        out[b * NQ * TQ + jj * TQ + t0 + tt] = gsh[jj][tt] - l;
    }
}

// ---------------------------------------------------------------------------
extern "C" void kernel_launch(void* const* d_in, const int* in_sizes, int n_in,
                              void* d_out, int out_size) {
    const float* emissions = (const float*)d_in[0];   // [B, N, T]
    const float* init      = (const float*)d_in[1];   // [N]
    const float* trans     = (const float*)d_in[2];   // [N, N]
    float* out = (float*)d_out;                       // [B, N, T]

    expT_kernel<<<dim3(TQ / 64, BQ), 256>>>(emissions);
    scan_kernel<<<dim3(BQ, 2), 128>>>(trans, init);
    gamma_kernel<<<dim3(TQ / 32, BQ), 256>>>(out);
}

// round 7
// speedup vs baseline: 2.8141x; 2.8141x over previous
#include <cuda_runtime.h>

#define BQ 64
#define NQ 64
#define TQ 4096
#define BN (BQ * NQ)     // 4096 floats per time slice
#define CCH 32           // chunks
#define LCH 128          // chunk length (CCH*LCH == TQ)

// Scratch: E = exp(emissions) in [t][b][j] layout, plus linear-domain
// alpha/beta (arbitrary per-(b,t) scale; cancels in gamma).
__device__ float g_E[TQ * BN];
__device__ float g_alpha[TQ * BN];
__device__ float g_beta[TQ * BN];

// ---------------------------------------------------------------------------
// Kernel 1: E[t][b][j] = exp(emissions[b][j][t])  (tiled transpose via shared)
// ---------------------------------------------------------------------------
__global__ void __launch_bounds__(256) expT_kernel(const float* __restrict__ em) {
    __shared__ float tile[64][65];
    int b  = blockIdx.y;
    int t0 = blockIdx.x * 64;
    int tid = threadIdx.x;
    int c  = tid & 63;
    int r4 = tid >> 6;

#pragma unroll
    for (int rep = 0; rep < 16; rep++) {
        int j = rep * 4 + r4;
        tile[j][c] = __expf(em[b * NQ * TQ + j * TQ + t0 + c]);
    }
    __syncthreads();
#pragma unroll
    for (int rep = 0; rep < 16; rep++) {
        int tt = rep * 4 + r4;
        g_E[(t0 + tt) * BN + b * NQ + c] = tile[c][tt];
    }
}

// ---------------------------------------------------------------------------
// Kernel 2: chunked forward/backward scans with warmup.
// grid (CCH, B, 2), 64 threads (1 thread per state, full 64-term dot).
// Interior chunks warm up 39 steps from an all-ones vector (direction
// converges via Hilbert-metric contraction of A; scale cancels in gamma).
// Renorm every 8 steps, pipelined (REDUCE publishes partials, APPLY applies
// 1/s one step later). E prefetch: 8 named slots, distance 8.
// ---------------------------------------------------------------------------

#define DOT_FULL(PBUF)                                                         \
    const float4* pv = (const float4*)&psh[PBUF][0];                           \
    float s0 = 0.f, s1 = 0.f, s2 = 0.f, s3 = 0.f;                              \
    _Pragma("unroll")                                                          \
    for (int k = 0; k < 16; k++) {                                             \
        float4 q = pv[k];                                                      \
        s0 = fmaf(q.x, A0[2 * k],     s0);                                     \
        s1 = fmaf(q.y, A1[2 * k],     s1);                                     \
        s2 = fmaf(q.z, A0[2 * k + 1], s2);                                     \
        s3 = fmaf(q.w, A1[2 * k + 1], s3);                                     \
    }                                                                          \
    float v2 = (s0 + s1) + (s2 + s3);

#define REDUCE_PUB()                                                           \
    {                                                                          \
        float s = v2;                                                          \
        s += __shfl_xor_sync(0xffffffffu, s, 1);                               \
        s += __shfl_xor_sync(0xffffffffu, s, 2);                               \
        s += __shfl_xor_sync(0xffffffffu, s, 4);                               \
        s += __shfl_xor_sync(0xffffffffu, s, 8);                               \
        s += __shfl_xor_sync(0xffffffffu, s, 16);                              \
        if (lane == 0) red[w] = s;                                             \
    }

// forward step at time T (runtime): consumes EREG = E[T]; refills with E[T+8]
#define FWD_STEP(T, EREG, APPLY, REDUCE) do {                                  \
    int tt_ = (T);                                                             \
    float e_new = g_E[((tt_ + 8 < TQ) ? tt_ + 8 : TQ - 1) * BN + ebase];       \
    if (APPLY) inv_s = __frcp_rn(red[0] + red[1]);                             \
    DOT_FULL((tt_ - 1) & 1)                                                    \
    if (APPLY) v2 *= inv_s;                                                    \
    v2 *= (EREG);                                                              \
    if (REDUCE) REDUCE_PUB()                                                   \
    if (tt_ >= wst) g_alpha[tt_ * BN + ebase] = v2;                            \
    psh[tt_ & 1][j] = v2;                                                      \
    __syncthreads();                                                           \
    (EREG) = e_new;                                                            \
} while (0)

// backward step at time T: EREG = E[T] feeds the carry; refills with E[T-8]
#define BWD_STEP(T, EREG, APPLY, REDUCE) do {                                  \
    int tt_ = (T);                                                             \
    float e_new = g_E[((tt_ >= 8) ? tt_ - 8 : 0) * BN + ebase];                \
    if (APPLY) inv_s = __frcp_rn(red[0] + red[1]);                             \
    DOT_FULL((tt_ + 1) & 1)                                                    \
    if (APPLY) v2 *= inv_s;                                                    \
    if (REDUCE) REDUCE_PUB()                                                   \
    if (tt_ <= wend) g_beta[tt_ * BN + ebase] = v2;                            \
    psh[tt_ & 1][j] = v2 * (EREG);                                             \
    __syncthreads();                                                           \
    (EREG) = e_new;                                                            \
} while (0)

__global__ void __launch_bounds__(64) scan_kernel(const float* __restrict__ trans,
                                                  const float* __restrict__ init) {
    const int c    = blockIdx.x;     // chunk
    const int b    = blockIdx.y;     // batch
    const int dir  = blockIdx.z;     // 0 fwd, 1 bwd
    const int j    = threadIdx.x;    // state 0..63
    const int lane = j & 31;
    const int w    = j >> 5;

    __shared__ __align__(16) float psh[2][64];
    __shared__ float red[2];

    float A0[32], A1[32];
    if (dir == 0) {
        // fwd: column j of A  (A0[k]=A[2k][j], A1[k]=A[2k+1][j])
#pragma unroll
        for (int k = 0; k < 32; k++) {
            A0[k] = trans[(2 * k) * NQ + j];
            A1[k] = trans[(2 * k + 1) * NQ + j];
        }
    } else {
        // bwd: row j of A (contiguous)
        const float2* row = (const float2*)(trans + j * NQ);
#pragma unroll
        for (int k = 0; k < 32; k++) {
            float2 p = row[k];
            A0[k] = p.x;
            A1[k] = p.y;
        }
    }

    const int ebase = b * NQ + j;
    float inv_s = 1.0f;

    if (dir == 0) {
        // -------- forward: write t in [c*L, (c+1)*L) --------
        const int wst = c * LCH;
        int t1, G;
        if (c == 0) {
            float v0 = init[j] * g_E[0 * BN + ebase];
            g_alpha[0 * BN + ebase] = v0;
            psh[0][j] = v0;          // time 0, parity 0
            t1 = 1;  G = 15;         // 7 + 15*8 = 127 steps: t = 1..127
        } else {
            t1 = c * LCH - 39;       // warmup starts here (39 steps)
            psh[(t1 - 1) & 1][j] = 1.0f;   // all-ones start vector
            G = 20;                  // 7 + 20*8 = 167 steps: t1 .. c*L+127
        }
        // prefill E slots: E[t1 .. t1+7]
        float e0 = g_E[(t1    ) * BN + ebase], e1 = g_E[(t1 + 1) * BN + ebase];
        float e2 = g_E[(t1 + 2) * BN + ebase], e3 = g_E[(t1 + 3) * BN + ebase];
        float e4 = g_E[(t1 + 4) * BN + ebase], e5 = g_E[(t1 + 5) * BN + ebase];
        float e6 = g_E[(t1 + 6) * BN + ebase], e7 = g_E[(t1 + 7) * BN + ebase];
        __syncthreads();

        // INIT7: t1..t1+6 (REDUCE at +5, APPLY at +6)
        FWD_STEP(t1,     e0, 0, 0); FWD_STEP(t1 + 1, e1, 0, 0);
        FWD_STEP(t1 + 2, e2, 0, 0); FWD_STEP(t1 + 3, e3, 0, 0);
        FWD_STEP(t1 + 4, e4, 0, 0); FWD_STEP(t1 + 5, e5, 0, 1);
        FWD_STEP(t1 + 6, e6, 1, 0);
        // groups of 8, slots rotated by 7
        for (int g = 0; g < G; g++) {
            int t = t1 + 7 + 8 * g;
            FWD_STEP(t,     e7, 0, 0); FWD_STEP(t + 1, e0, 0, 0);
            FWD_STEP(t + 2, e1, 0, 0); FWD_STEP(t + 3, e2, 0, 0);
            FWD_STEP(t + 4, e3, 0, 0); FWD_STEP(t + 5, e4, 0, 0);
            FWD_STEP(t + 6, e5, 0, 1); FWD_STEP(t + 7, e6, 1, 0);
        }
    } else {
        // -------- backward: write t in [c*L, (c+1)*L) --------
        const int wend = (c + 1) * LCH - 1;
        int te, G;
        if (c == CCH - 1) {
            te = TQ - 1;
            g_beta[te * BN + ebase] = 1.0f;
            psh[te & 1][j] = g_E[te * BN + ebase];   // carry = beta*E at T-1
            G = 15;                                  // steps: 4094..3968
        } else {
            te = (c + 1) * LCH + 39;                 // warmup start time
            psh[te & 1][j] = g_E[te * BN + ebase];   // beta = ones at te
            G = 20;                                  // 167 steps: te-1 .. c*L
        }
        int t1 = te - 1;
        // prefill E slots: E[t1 .. t1-7]
        float e0 = g_E[(t1    ) * BN + ebase], e1 = g_E[(t1 - 1) * BN + ebase];
        float e2 = g_E[(t1 - 2) * BN + ebase], e3 = g_E[(t1 - 3) * BN + ebase];
        float e4 = g_E[(t1 - 4) * BN + ebase], e5 = g_E[(t1 - 5) * BN + ebase];
        float e6 = g_E[(t1 - 6) * BN + ebase], e7 = g_E[(t1 - 7) * BN + ebase];
        __syncthreads();

        // INIT7: t1..t1-6
        BWD_STEP(t1,     e0, 0, 0); BWD_STEP(t1 - 1, e1, 0, 0);
        BWD_STEP(t1 - 2, e2, 0, 0); BWD_STEP(t1 - 3, e3, 0, 0);
        BWD_STEP(t1 - 4, e4, 0, 0); BWD_STEP(t1 - 5, e5, 0, 1);
        BWD_STEP(t1 - 6, e6, 1, 0);
        for (int g = 0; g < G; g++) {
            int t = t1 - 7 - 8 * g;
            BWD_STEP(t,     e7, 0, 0); BWD_STEP(t - 1, e0, 0, 0);
            BWD_STEP(t - 2, e1, 0, 0); BWD_STEP(t - 3, e2, 0, 0);
            BWD_STEP(t - 4, e3, 0, 0); BWD_STEP(t - 5, e4, 0, 0);
            BWD_STEP(t - 6, e5, 0, 1); BWD_STEP(t - 7, e6, 1, 0);
        }
    }
}

// ---------------------------------------------------------------------------
// Kernel 3: gamma. g = log(alpha)+log(beta); out = g - LSE_j(g).
// Scales cancel. Tiled so output writes coalesce along t.
// ---------------------------------------------------------------------------
__global__ void __launch_bounds__(256) gamma_kernel(float* __restrict__ out) {
    __shared__ float gsh[64][33];
    __shared__ float part[8][32];
    __shared__ float lse[32];

    int b   = blockIdx.y;
    int t0  = blockIdx.x * 32;
    int tid = threadIdx.x;
    int c   = tid & 63;
    int r   = tid >> 6;

#pragma unroll
    for (int rep = 0; rep < 8; rep++) {
        int tt  = rep * 4 + r;
        int idx = (t0 + tt) * BN + b * NQ + c;
        gsh[c][tt] = __logf(g_alpha[idx]) + __logf(g_beta[idx]);
    }
    __syncthreads();

    int tt  = tid & 31;
    int seg = tid >> 5;

    float m = -3.4e38f;
#pragma unroll
    for (int k = 0; k < 8; k++) m = fmaxf(m, gsh[seg * 8 + k][tt]);
    part[seg][tt] = m;
    __syncthreads();

    if (seg == 0) {
        float mm = part[0][tt];
#pragma unroll
        for (int k = 1; k < 8; k++) mm = fmaxf(mm, part[k][tt]);
        lse[tt] = mm;
    }
    __syncthreads();

    float mm = lse[tt];
    float ss = 0.f;
#pragma unroll
    for (int k = 0; k < 8; k++) ss += __expf(gsh[seg * 8 + k][tt] - mm);
    part[seg][tt] = ss;
    __syncthreads();

    if (seg == 0) {
        float s = 0.f;
#pragma unroll
        for (int k = 0; k < 8; k++) s += part[k][tt];
        lse[tt] = mm + __logf(s);
    }
    __syncthreads();

    float l = lse[tt];
#pragma unroll
    for (int rep = 0; rep < 8; rep++) {
        int jj = rep * 8 + seg;
        out[b * NQ * TQ + jj * TQ + t0 + tt] = gsh[jj][tt] - l;
    }
}

// ---------------------------------------------------------------------------
extern "C" void kernel_launch(void* const* d_in, const int* in_sizes, int n_in,
                              void* d_out, int out_size) {
    const float* emissions = (const float*)d_in[0];   // [B, N, T]
    const float* init      = (const float*)d_in[1];   // [N]
    const float* trans     = (const float*)d_in[2];   // [N, N]
    float* out = (float*)d_out;                       // [B, N, T]

    expT_kernel<<<dim3(TQ / 64, BQ), 256>>>(emissions);
    scan_kernel<<<dim3(CCH, BQ, 2), 64>>>(trans, init);
    gamma_kernel<<<dim3(TQ / 32, BQ), 256>>>(out);
}

// round 8
// speedup vs baseline: 2.9129x; 1.0351x over previous
#include <cuda_runtime.h>

#define BQ 64
#define NQ 64
#define TQ 4096
#define BN (BQ * NQ)     // 4096 floats per time slice
#define CCH 16           // chunks
#define LCH 256          // chunk length (CCH*LCH == TQ)

// Scratch: E = exp(emissions) in [t][b][j] layout, plus linear-domain
// alpha/beta (arbitrary per-(b,t) scale; cancels in gamma).
__device__ float g_E[TQ * BN];
__device__ float g_alpha[TQ * BN];
__device__ float g_beta[TQ * BN];

// ---- packed f32x2 helpers (one instr = 2 fp32 FMAs on the FMA pipe) ----
__device__ __forceinline__ void fma2(unsigned long long& d,
                                     unsigned long long a, unsigned long long b) {
    asm("fma.rn.f32x2 %0, %1, %2, %0;" : "+l"(d) : "l"(a), "l"(b));
}
__device__ __forceinline__ unsigned long long add2(unsigned long long a,
                                                   unsigned long long b) {
    unsigned long long d;
    asm("add.rn.f32x2 %0, %1, %2;" : "=l"(d) : "l"(a), "l"(b));
    return d;
}
__device__ __forceinline__ unsigned long long pack2(float lo, float hi) {
    unsigned long long d;
    asm("mov.b64 %0, {%1, %2};" : "=l"(d) : "f"(lo), "f"(hi));
    return d;
}
__device__ __forceinline__ float2 unpack2(unsigned long long v) {
    float2 r;
    asm("mov.b64 {%0, %1}, %2;" : "=f"(r.x), "=f"(r.y) : "l"(v));
    return r;
}

// ---------------------------------------------------------------------------
// Kernel 1: E[t][b][j] = exp(emissions[b][j][t])  (tiled transpose via shared)
// ---------------------------------------------------------------------------
__global__ void __launch_bounds__(256) expT_kernel(const float* __restrict__ em) {
    __shared__ float tile[64][65];
    int b  = blockIdx.y;
    int t0 = blockIdx.x * 64;
    int tid = threadIdx.x;
    int c  = tid & 63;
    int r4 = tid >> 6;

#pragma unroll
    for (int rep = 0; rep < 16; rep++) {
        int j = rep * 4 + r4;
        tile[j][c] = __expf(em[b * NQ * TQ + j * TQ + t0 + c]);
    }
    __syncthreads();
#pragma unroll
    for (int rep = 0; rep < 16; rep++) {
        int tt = rep * 4 + r4;
        g_E[(t0 + tt) * BN + b * NQ + c] = tile[c][tt];
    }
}

// ---------------------------------------------------------------------------
// Kernel 2: chunked forward/backward scans with warmup.
// grid (CCH, B, 2), 64 threads (1 thread per state; 64-term dot as 32 packed
// f32x2 FMAs). Interior chunks warm up 39 steps from an all-ones vector
// (Hilbert-metric contraction of A; uniform scale cancels in gamma).
// Renorm every 8 steps, pipelined. E prefetch: 8 named slots, distance 8.
// ---------------------------------------------------------------------------

#define DOT_FULL(PBUF)                                                         \
    const ulonglong2* pv = (const ulonglong2*)&psh[PBUF][0];                   \
    unsigned long long ac0 = 0, ac1 = 0, ac2 = 0, ac3 = 0;                     \
    _Pragma("unroll")                                                          \
    for (int k = 0; k < 16; k++) {                                             \
        ulonglong2 q = pv[k];                                                  \
        fma2((k & 1) ? ac2 : ac0, q.x, Apk[2 * k]);                            \
        fma2((k & 1) ? ac3 : ac1, q.y, Apk[2 * k + 1]);                        \
    }                                                                          \
    float2 fr = unpack2(add2(add2(ac0, ac1), add2(ac2, ac3)));                 \
    float v2 = fr.x + fr.y;

#define REDUCE_PUB()                                                           \
    {                                                                          \
        float s = v2;                                                          \
        s += __shfl_xor_sync(0xffffffffu, s, 1);                               \
        s += __shfl_xor_sync(0xffffffffu, s, 2);                               \
        s += __shfl_xor_sync(0xffffffffu, s, 4);                               \
        s += __shfl_xor_sync(0xffffffffu, s, 8);                               \
        s += __shfl_xor_sync(0xffffffffu, s, 16);                              \
        if (lane == 0) red[w] = s;                                             \
    }

// forward step at time T (runtime): consumes EREG = E[T]; refills with E[T+8]
#define FWD_STEP(T, EREG, APPLY, REDUCE) do {                                  \
    int tt_ = (T);                                                             \
    float e_new = g_E[((tt_ + 8 < TQ) ? tt_ + 8 : TQ - 1) * BN + ebase];       \
    if (APPLY) inv_s = __frcp_rn(red[0] + red[1]);                             \
    DOT_FULL((tt_ - 1) & 1)                                                    \
    if (APPLY) v2 *= inv_s;                                                    \
    v2 *= (EREG);                                                              \
    if (REDUCE) REDUCE_PUB()                                                   \
    if (tt_ >= wst) g_alpha[tt_ * BN + ebase] = v2;                            \
    psh[tt_ & 1][j] = v2;                                                      \
    __syncthreads();                                                           \
    (EREG) = e_new;                                                            \
} while (0)

// backward step at time T: EREG = E[T] feeds the carry; refills with E[T-8]
#define BWD_STEP(T, EREG, APPLY, REDUCE) do {                                  \
    int tt_ = (T);                                                             \
    float e_new = g_E[((tt_ >= 8) ? tt_ - 8 : 0) * BN + ebase];                \
    if (APPLY) inv_s = __frcp_rn(red[0] + red[1]);                             \
    DOT_FULL((tt_ + 1) & 1)                                                    \
    if (APPLY) v2 *= inv_s;                                                    \
    if (REDUCE) REDUCE_PUB()                                                   \
    if (tt_ <= wend) g_beta[tt_ * BN + ebase] = v2;                            \
    psh[tt_ & 1][j] = v2 * (EREG);                                             \
    __syncthreads();                                                           \
    (EREG) = e_new;                                                            \
} while (0)

__global__ void __launch_bounds__(64) scan_kernel(const float* __restrict__ trans,
                                                  const float* __restrict__ init) {
    const int c    = blockIdx.x;     // chunk
    const int b    = blockIdx.y;     // batch
    const int dir  = blockIdx.z;     // 0 fwd, 1 bwd
    const int j    = threadIdx.x;    // state 0..63
    const int lane = j & 31;
    const int w    = j >> 5;

    __shared__ __align__(16) float psh[2][64];
    __shared__ float red[2];

    // 64 A-coefficients per thread, packed once into 32 f32x2 registers.
    // Pairing matches DOT_FULL: Apk[2k] hits states (4k,4k+1), Apk[2k+1]
    // hits (4k+2,4k+3).
    unsigned long long Apk[32];
    if (dir == 0) {
        // fwd: column j of A (one-time strided loads)
#pragma unroll
        for (int k = 0; k < 16; k++) {
            int i0 = 4 * k;
            Apk[2 * k]     = pack2(trans[(i0    ) * NQ + j], trans[(i0 + 1) * NQ + j]);
            Apk[2 * k + 1] = pack2(trans[(i0 + 2) * NQ + j], trans[(i0 + 3) * NQ + j]);
        }
    } else {
        // bwd: row j of A (contiguous)
        const float4* rp = (const float4*)(trans + j * NQ);
#pragma unroll
        for (int k = 0; k < 16; k++) {
            float4 a = rp[k];
            Apk[2 * k]     = pack2(a.x, a.y);
            Apk[2 * k + 1] = pack2(a.z, a.w);
        }
    }

    const int ebase = b * NQ + j;
    float inv_s = 1.0f;

    if (dir == 0) {
        // -------- forward: write t in [c*L, (c+1)*L) --------
        const int wst = c * LCH;
        int t1, G;
        if (c == 0) {
            float v0 = init[j] * g_E[0 * BN + ebase];
            g_alpha[0 * BN + ebase] = v0;
            psh[0][j] = v0;          // time 0, parity 0
            t1 = 1;  G = 31;         // 7 + 31*8 = 255 steps: t = 1..255
        } else {
            t1 = c * LCH - 39;       // warmup starts here (39 steps)
            psh[(t1 - 1) & 1][j] = 1.0f;   // all-ones start vector
            G = 36;                  // 7 + 36*8 = 295 steps: t1 .. c*L+255
        }
        // prefill E slots: E[t1 .. t1+7]
        float e0 = g_E[(t1    ) * BN + ebase], e1 = g_E[(t1 + 1) * BN + ebase];
        float e2 = g_E[(t1 + 2) * BN + ebase], e3 = g_E[(t1 + 3) * BN + ebase];
        float e4 = g_E[(t1 + 4) * BN + ebase], e5 = g_E[(t1 + 5) * BN + ebase];
        float e6 = g_E[(t1 + 6) * BN + ebase], e7 = g_E[(t1 + 7) * BN + ebase];
        __syncthreads();

        // INIT7: t1..t1+6 (REDUCE at +5, APPLY at +6)
        FWD_STEP(t1,     e0, 0, 0); FWD_STEP(t1 + 1, e1, 0, 0);
        FWD_STEP(t1 + 2, e2, 0, 0); FWD_STEP(t1 + 3, e3, 0, 0);
        FWD_STEP(t1 + 4, e4, 0, 0); FWD_STEP(t1 + 5, e5, 0, 1);
        FWD_STEP(t1 + 6, e6, 1, 0);
        // groups of 8, slots rotated by 7
        for (int g = 0; g < G; g++) {
            int t = t1 + 7 + 8 * g;
            FWD_STEP(t,     e7, 0, 0); FWD_STEP(t + 1, e0, 0, 0);
            FWD_STEP(t + 2, e1, 0, 0); FWD_STEP(t + 3, e2, 0, 0);
            FWD_STEP(t + 4, e3, 0, 0); FWD_STEP(t + 5, e4, 0, 0);
            FWD_STEP(t + 6, e5, 0, 1); FWD_STEP(t + 7, e6, 1, 0);
        }
    } else {
        // -------- backward: write t in [c*L, (c+1)*L) --------
        const int wend = (c + 1) * LCH - 1;
        int te, G;
        if (c == CCH - 1) {
            te = TQ - 1;
            g_beta[te * BN + ebase] = 1.0f;
            psh[te & 1][j] = g_E[te * BN + ebase];   // carry = beta*E at T-1
            G = 31;                                  // 255 steps: 4094..3840
        } else {
            te = (c + 1) * LCH + 39;                 // warmup start time
            psh[te & 1][j] = g_E[te * BN + ebase];   // beta = ones at te
            G = 36;                                  // 295 steps: te-1 .. c*L
        }
        int t1 = te - 1;
        // prefill E slots: E[t1 .. t1-7]
        float e0 = g_E[(t1    ) * BN + ebase], e1 = g_E[(t1 - 1) * BN + ebase];
        float e2 = g_E[(t1 - 2) * BN + ebase], e3 = g_E[(t1 - 3) * BN + ebase];
        float e4 = g_E[(t1 - 4) * BN + ebase], e5 = g_E[(t1 - 5) * BN + ebase];
        float e6 = g_E[(t1 - 6) * BN + ebase], e7 = g_E[(t1 - 7) * BN + ebase];
        __syncthreads();

        // INIT7: t1..t1-6
        BWD_STEP(t1,     e0, 0, 0); BWD_STEP(t1 - 1, e1, 0, 0);
        BWD_STEP(t1 - 2, e2, 0, 0); BWD_STEP(t1 - 3, e3, 0, 0);
        BWD_STEP(t1 - 4, e4, 0, 0); BWD_STEP(t1 - 5, e5, 0, 1);
        BWD_STEP(t1 - 6, e6, 1, 0);
        for (int g = 0; g < G; g++) {
            int t = t1 - 7 - 8 * g;
            BWD_STEP(t,     e7, 0, 0); BWD_STEP(t - 1, e0, 0, 0);
            BWD_STEP(t - 2, e1, 0, 0); BWD_STEP(t - 3, e2, 0, 0);
            BWD_STEP(t - 4, e3, 0, 0); BWD_STEP(t - 5, e4, 0, 0);
            BWD_STEP(t - 6, e5, 0, 1); BWD_STEP(t - 7, e6, 1, 0);
        }
    }
}

// ---------------------------------------------------------------------------
// Kernel 3: gamma. g = log(alpha)+log(beta); out = g - LSE_j(g).
// Scales cancel. Tiled so output writes coalesce along t.
// ---------------------------------------------------------------------------
__global__ void __launch_bounds__(256) gamma_kernel(float* __restrict__ out) {
    __shared__ float gsh[64][33];
    __shared__ float part[8][32];
    __shared__ float lse[32];

    int b   = blockIdx.y;
    int t0  = blockIdx.x * 32;
    int tid = threadIdx.x;
    int c   = tid & 63;
    int r   = tid >> 6;

#pragma unroll
    for (int rep = 0; rep < 8; rep++) {
        int tt  = rep * 4 + r;
        int idx = (t0 + tt) * BN + b * NQ + c;
        gsh[c][tt] = __logf(g_alpha[idx]) + __logf(g_beta[idx]);
    }
    __syncthreads();

    int tt  = tid & 31;
    int seg = tid >> 5;

    float m = -3.4e38f;
#pragma unroll
    for (int k = 0; k < 8; k++) m = fmaxf(m, gsh[seg * 8 + k][tt]);
    part[seg][tt] = m;
    __syncthreads();

    if (seg == 0) {
        float mm = part[0][tt];
#pragma unroll
        for (int k = 1; k < 8; k++) mm = fmaxf(mm, part[k][tt]);
        lse[tt] = mm;
    }
    __syncthreads();

    float mm = lse[tt];
    float ss = 0.f;
#pragma unroll
    for (int k = 0; k < 8; k++) ss += __expf(gsh[seg * 8 + k][tt] - mm);
    part[seg][tt] = ss;
    __syncthreads();

    if (seg == 0) {
        float s = 0.f;
#pragma unroll
        for (int k = 0; k < 8; k++) s += part[k][tt];
        lse[tt] = mm + __logf(s);
    }
    __syncthreads();

    float l = lse[tt];
#pragma unroll
    for (int rep = 0; rep < 8; rep++) {
        int jj = rep * 8 + seg;
        out[b * NQ * TQ + jj * TQ + t0 + tt] = gsh[jj][tt] - l;
    }
}

// ---------------------------------------------------------------------------
extern "C" void kernel_launch(void* const* d_in, const int* in_sizes, int n_in,
                              void* d_out, int out_size) {
    const float* emissions = (const float*)d_in[0];   // [B, N, T]
    const float* init      = (const float*)d_in[1];   // [N]
    const float* trans     = (const float*)d_in[2];   // [N, N]
    float* out = (float*)d_out;                       // [B, N, T]

    expT_kernel<<<dim3(TQ / 64, BQ), 256>>>(emissions);
    scan_kernel<<<dim3(CCH, BQ, 2), 64>>>(trans, init);
    gamma_kernel<<<dim3(TQ / 32, BQ), 256>>>(out);
}